// round 11
// baseline (speedup 1.0000x reference)
#include <cuda_runtime.h>
#include <cuda_bf16.h>
#include <cstdint>

// ---------------- problem constants ----------------
#define NPMAX   2400000
#define GX      432
#define GY      496
#define NVOX    (GX*GY)        // 214272 (z dim = 1)
#define MAXV    40000
#define MAXP    32
#define CAP     64             // per-voxel bucket capacity (max count ~35, P(>64) ~ e^-60)
#define CHUNK   8192           // points per k_rank block (8/thread)
#define SENTINEL 0x7FFFFFFF

// ---------------- device scratch (static: no allocations allowed) ----------------
__device__ int g_first[NVOX];       // min original point index per voxel
__device__ int g_cnt[NVOX];         // total arrivals per voxel
__device__ int g_vlist[MAXV];       // slot -> packed (cnt<<18 | lin), -1 = empty
__device__ int g_vbuf[NVOX * CAP];  // per-voxel point indices (unordered set)
__device__ int g_hist[512];         // per-rank-block first-occurrence counts

// ---------------- voxel coordinate ----------------
// Mirror of what XLA computes for (p - pc_min) / voxel_size: div-by-constant
// rewritten to mul-by-RN(1/const). RN(1/0.16f)=6.25f exactly; RN(1/4)=0.25f.
// Intrinsics block FMA contraction. (Verified bit-exact: rel_err == 0.0.)
__device__ __forceinline__ int point_lin(float4 p) {
    float fx = floorf(__fmul_rn(__fsub_rn(p.x,   0.0f), 6.25f));
    float fy = floorf(__fmul_rn(__fsub_rn(p.y, -39.68f), 6.25f));
    float fz = floorf(__fmul_rn(__fsub_rn(p.z,  -3.0f), 0.25f));
    bool valid = (fx >= 0.f) & (fx < (float)GX) &
                 (fy >= 0.f) & (fy < (float)GY) &
                 (fz >= 0.f) & (fz < 1.f);
    if (!valid) return -1;
    return (int)fy * GX + (int)fx;   // z == 0
}

__device__ __forceinline__ int warpInclScan(int v, int lane) {
    #pragma unroll
    for (int o = 1; o < 32; o <<= 1) {
        int t = __shfl_up_sync(0xffffffffu, v, o);
        if (lane >= o) v += t;
    }
    return v;
}

// ---------------- kernels ----------------
__global__ void k_init(float* __restrict__ o_coor) {
    int i = blockIdx.x * blockDim.x + threadIdx.x;
    if (i < NVOX) { g_first[i] = SENTINEL; g_cnt[i] = 0; }
    if (i < MAXV)  g_vlist[i] = -1;
    if (i < MAXV * 3) o_coor[i] = -1.0f;
    if (i < 512)   g_hist[i] = 0;
}

__global__ void k_point(const float4* __restrict__ pts, int n) {
    int i = blockIdx.x * blockDim.x + threadIdx.x;
    if (i >= n) return;
    int lin = point_lin(pts[i]);
    if (lin < 0) return;
    atomicMin(&g_first[lin], i);               // return unused -> RED.MIN
    int j = atomicAdd(&g_cnt[lin], 1);
    if (j < CAP) g_vbuf[lin * CAP + j] = i;    // unordered set; order fixed later by rank
}

// Per-rank-block first-occurrence counts, straight from g_first:
// block b's mark total == #voxels with g_first in [b*CHUNK, (b+1)*CHUNK).
// One 0.9 MB pass instead of a 2.4M-point mark scan.
__global__ void k_hist() {
    int v = blockIdx.x * blockDim.x + threadIdx.x;
    if (v >= NVOX) return;
    int f = g_first[v];
    if (f != SENTINEL) atomicAdd(&g_hist[f / CHUNK], 1);
}

// Slot assignment. Each block derives its exact exclusive offset by reducing
// g_hist[0..bid) (<=293 ints). Blocks entirely past the MAXV budget exit
// before touching ANY point data (~98% of blocks). Active blocks (~6) read
// their 8192 points from pts directly and scan their marks.
__global__ void k_rank(const float4* __restrict__ pts, int n,
                       float* __restrict__ o_coor) {
    __shared__ int warpTot[32];
    int tid = threadIdx.x;
    int lane = tid & 31, w = tid >> 5;
    int bid = blockIdx.x;

    // ---- exclusive offset = sum of preceding block counts ----
    int v = (tid < bid) ? g_hist[tid] : 0;     // nb <= 512 <= blockDim
    #pragma unroll
    for (int o = 16; o > 0; o >>= 1) v += __shfl_down_sync(0xffffffffu, v, o);
    if (lane == 0) warpTot[w] = v;
    __syncthreads();
    if (w == 0) {
        int t = warpTot[lane];
        #pragma unroll
        for (int o = 16; o > 0; o >>= 1) t += __shfl_down_sync(0xffffffffu, t, o);
        if (lane == 0) warpTot[0] = t;
    }
    __syncthreads();
    int off = warpTot[0];
    if (off >= MAXV) return;                   // no point data touched
    __syncthreads();                           // warpTot reused below

    // ---- marks for 8 consecutive points, straight from pts ----
    int base = bid * CHUNK + tid * 8;
    int lin[8], m[8];
    int s = 0;
    #pragma unroll
    for (int k = 0; k < 8; k++) {
        int i = base + k;
        int l = (i < n) ? point_lin(pts[i]) : -1;
        lin[k] = l;
        m[k] = (l >= 0 && g_first[l] == i) ? 1 : 0;
        s += m[k];
    }

    // ---- block scan: warp shfl scan + warp-aggregate scan (2 barriers) ----
    int inc = warpInclScan(s, lane);
    if (lane == 31) warpTot[w] = inc;
    __syncthreads();
    if (w == 0) warpTot[lane] = warpInclScan(warpTot[lane], lane);
    __syncthreads();
    int ex = inc + ((w > 0) ? warpTot[w - 1] : 0) - s;   // block-local exclusive

    int r = off + ex;
    #pragma unroll
    for (int k = 0; k < 8; k++) {
        if (m[k]) {
            if (r < MAXV) {
                int c = min(g_cnt[lin[k]], CAP);
                g_vlist[r] = lin[k] | (c << 18);        // pack voxel id + clamped count
                int x = lin[k] % GX, y = lin[k] / GX;   // z == 0
                o_coor[r * 3 + 0] = 0.0f;
                o_coor[r * 3 + 1] = (float)y;
                o_coor[r * 3 + 2] = (float)x;
            }
            r++;
        }
    }
}

// One warp per slot. Ranks bucket entries by original point index (distinct ->
// permutation), writes point rows at their ranks, and ZEROES padding rows
// itself (no global memset):
//   n==0      : all 32 rows zeroed (lanes write row==lane)
//   0<n<=32   : ranks cover [0,n); lanes >= n zero rows [n,32)
//   n>32      : 32 entries have rank < 32 -> all rows rank-written
__global__ void k_emit(const float4* __restrict__ pts,
                       float4* __restrict__ o_vox,
                       float* __restrict__ o_np) {
    int s = blockIdx.x * 8 + (threadIdx.x >> 5);
    if (s >= MAXV) return;
    int lane = threadIdx.x & 31;
    int v = g_vlist[s];
    int lin = v & 0x3FFFF;
    int n = (v >= 0) ? (v >> 18) : 0;    // clamped to CAP at pack time
    if (lane == 0) o_np[s] = (float)min(n, MAXP);
    float4* row = o_vox + (size_t)s * MAXP;
    const float4 z4 = make_float4(0.f, 0.f, 0.f, 0.f);

    if (n <= 32) {                       // common case (incl. empty slots)
        int m = n;
        const int* buf = &g_vbuf[lin * CAP];
        int e0 = (v >= 0 && lane < m) ? buf[lane] : SENTINEL;
        int r0 = 0;
        for (int j = 0; j < m; j++) {    // m uniform across the warp
            int a = __shfl_sync(0xffffffffu, e0, j);
            r0 += (a < e0) ? 1 : 0;
        }
        if (lane < m) row[r0] = pts[e0];
        else          row[lane] = z4;    // zero padding rows [m, 32)
    } else {                             // rare: up to 64 entries, keep ranks < 32
        int m = n;                       // already min(cnt, CAP)
        const int* buf = &g_vbuf[lin * CAP];
        int e0 = (lane      < m) ? buf[lane]      : SENTINEL;
        int e1 = (lane + 32 < m) ? buf[lane + 32] : SENTINEL;
        int r0 = 0, r1 = 0;
        #pragma unroll
        for (int j = 0; j < 32; j++) {
            int a = __shfl_sync(0xffffffffu, e0, j);
            int b = __shfl_sync(0xffffffffu, e1, j);
            r0 += (a < e0) + (b < e0);
            r1 += (a < e1) + (b < e1);
        }
        if (e0 != SENTINEL && r0 < MAXP) row[r0] = pts[e0];
        if (e1 != SENTINEL && r1 < MAXP) row[r1] = pts[e1];
    }
}

// ---------------- launch ----------------
extern "C" void kernel_launch(void* const* d_in, const int* in_sizes, int n_in,
                              void* d_out, int out_size) {
    const float4* pts = (const float4*)d_in[0];
    int n = in_sizes[0] / 4;
    if (n > NPMAX) n = NPMAX;

    float* out    = (float*)d_out;
    float* o_coor = out + (size_t)MAXV * MAXP * 4;   // 5,120,000
    float* o_np   = o_coor + (size_t)MAXV * 3;       // +120,000

    int nb = (n + CHUNK - 1) / CHUNK;                // 293 for n = 2.4M

    k_init <<<(NVOX + 255) / 256, 256>>>(o_coor);
    k_point<<<(n + 255) / 256, 256>>>(pts, n);
    k_hist <<<(NVOX + 1023) / 1024, 1024>>>();
    k_rank <<<nb, 1024>>>(pts, n, o_coor);
    k_emit <<<(MAXV + 7) / 8, 256>>>(pts, (float4*)out, o_np);
}

// round 14
// speedup vs baseline: 1.4959x; 1.4959x over previous
#include <cuda_runtime.h>
#include <cuda_bf16.h>
#include <cstdint>

// ---------------- problem constants ----------------
#define NPMAX   2400000
#define GX      432
#define GY      496
#define NVOX    (GX*GY)        // 214272 (z dim = 1)
#define MAXV    40000
#define MAXP    32
#define CAP     64             // per-voxel bucket capacity (max count ~35, P(>64) ~ e^-60)
#define CHUNK   2048           // points per k_rank block (8/thread, 256 threads)
#define CHSH    11             // log2(CHUNK)
#define NHIST   2048           // >= nb = ceil(NPMAX/CHUNK) = 1172
#define SENTINEL 0x7FFFFFFF

// ---------------- device scratch (static: no allocations allowed) ----------------
__device__ int g_first[NVOX];       // min original point index per voxel
__device__ int g_cnt[NVOX];         // total arrivals per voxel
__device__ int g_vlist[MAXV];       // slot -> packed (cnt<<18 | lin), -1 = empty
__device__ int g_vbuf[NVOX * CAP];  // per-voxel point indices (unordered set)
__device__ int g_hist[NHIST];       // per-chunk first-occurrence counts
__device__ int g_hoff[NHIST];       // exclusive prefix of g_hist

// ---------------- voxel coordinate ----------------
// Mirror of what XLA computes for (p - pc_min) / voxel_size: div-by-constant
// rewritten to mul-by-RN(1/const). RN(1/0.16f)=6.25f exactly; RN(1/4)=0.25f.
// Intrinsics block FMA contraction. (Verified bit-exact: rel_err == 0.0.)
__device__ __forceinline__ int point_lin(float4 p) {
    float fx = floorf(__fmul_rn(__fsub_rn(p.x,   0.0f), 6.25f));
    float fy = floorf(__fmul_rn(__fsub_rn(p.y, -39.68f), 6.25f));
    float fz = floorf(__fmul_rn(__fsub_rn(p.z,  -3.0f), 0.25f));
    bool valid = (fx >= 0.f) & (fx < (float)GX) &
                 (fy >= 0.f) & (fy < (float)GY) &
                 (fz >= 0.f) & (fz < 1.f);
    if (!valid) return -1;
    return (int)fy * GX + (int)fx;   // z == 0
}

// All 32 lanes of the calling warp MUST execute this (full-mask shuffles).
__device__ __forceinline__ int warpInclScan(int v, int lane) {
    #pragma unroll
    for (int o = 1; o < 32; o <<= 1) {
        int t = __shfl_up_sync(0xffffffffu, v, o);
        if (lane >= o) v += t;
    }
    return v;
}

// ---------------- kernels ----------------
__global__ void k_init(float* __restrict__ o_coor) {
    int i = blockIdx.x * blockDim.x + threadIdx.x;
    if (i < NVOX) { g_first[i] = SENTINEL; g_cnt[i] = 0; }
    if (i < MAXV)  g_vlist[i] = -1;
    if (i < MAXV * 3) o_coor[i] = -1.0f;
    if (i < NHIST) g_hist[i] = 0;
}

__global__ void k_point(const float4* __restrict__ pts, int n) {
    int i = blockIdx.x * blockDim.x + threadIdx.x;
    if (i >= n) return;
    int lin = point_lin(pts[i]);
    if (lin < 0) return;
    atomicMin(&g_first[lin], i);               // return unused -> RED.MIN
    int j = atomicAdd(&g_cnt[lin], 1);
    if (j < CAP) g_vbuf[lin * CAP + j] = i;    // unordered set; order fixed later by rank
}

// Per-chunk first-occurrence counts, straight from g_first (0.9 MB pass):
// chunk b's mark total == #voxels with g_first in [b*CHUNK, (b+1)*CHUNK).
__global__ void k_hist() {
    int v = blockIdx.x * blockDim.x + threadIdx.x;
    if (v >= NVOX) return;
    int f = g_first[v];
    if (f != SENTINEL) atomicAdd(&g_hist[f >> CHSH], 1);
}

// Single block: exclusive scan of all NHIST=2048 bucket counts (2 per thread).
__global__ void k_off() {
    __shared__ int warpTot[32];
    int tid = threadIdx.x;               // 1024 threads
    int lane = tid & 31, w = tid >> 5;
    int a = g_hist[2 * tid];
    int b = g_hist[2 * tid + 1];
    int s = a + b;
    int inc = warpInclScan(s, lane);
    if (lane == 31) warpTot[w] = inc;
    __syncthreads();
    if (w == 0) warpTot[lane] = warpInclScan(warpTot[lane], lane);  // all 32 lanes
    __syncthreads();
    int ex = inc + ((w > 0) ? warpTot[w - 1] : 0) - s;   // exclusive over pairs
    g_hoff[2 * tid]     = ex;
    g_hoff[2 * tid + 1] = ex + a;
}

// Slot assignment. Inactive blocks (offset already past MAXV: ~98%) do ONE
// load and return. Active blocks (~22, 256 threads, 8 pts/thread) recompute
// point_lin from pts directly and block-scan their first-occurrence marks.
__global__ void k_rank(const float4* __restrict__ pts, int n,
                       float* __restrict__ o_coor) {
    int bid = blockIdx.x;
    int off = g_hoff[bid];               // broadcast load
    if (off >= MAXV) return;

    __shared__ int warpTot[8];
    int tid = threadIdx.x;               // 256 threads
    int lane = tid & 31, w = tid >> 5;

    int base = bid * CHUNK + tid * 8;
    int lin[8], m[8];
    int s = 0;
    #pragma unroll
    for (int k = 0; k < 8; k++) {
        int i = base + k;
        int l = (i < n) ? point_lin(pts[i]) : -1;
        lin[k] = l;
        m[k] = (l >= 0 && g_first[l] == i) ? 1 : 0;
        s += m[k];
    }

    // block scan: warp shfl scan + 8-warp aggregate scan (2 barriers).
    // The aggregate scan runs on ALL 32 lanes of warp 0 (lanes >= 8 carry 0)
    // so the full-mask shuffles inside warpInclScan are non-divergent.
    int inc = warpInclScan(s, lane);
    if (lane == 31) warpTot[w] = inc;
    __syncthreads();
    if (w == 0) {
        int t = (lane < 8) ? warpTot[lane] : 0;
        t = warpInclScan(t, lane);
        if (lane < 8) warpTot[lane] = t;
    }
    __syncthreads();
    int ex = inc + ((w > 0) ? warpTot[w - 1] : 0) - s;

    int r = off + ex;
    #pragma unroll
    for (int k = 0; k < 8; k++) {
        if (m[k]) {
            if (r < MAXV) {
                int c = min(g_cnt[lin[k]], CAP);
                g_vlist[r] = lin[k] | (c << 18);        // pack voxel id + clamped count
                int x = lin[k] % GX, y = lin[k] / GX;   // z == 0
                o_coor[r * 3 + 0] = 0.0f;
                o_coor[r * 3 + 1] = (float)y;
                o_coor[r * 3 + 2] = (float)x;
            }
            r++;
        }
    }
}

// One warp per slot. Ranks bucket entries by original point index (distinct ->
// permutation), writes point rows at their ranks, and ZEROES padding rows
// itself (no global memset):
//   n==0      : all 32 rows zeroed (lanes write row==lane)
//   0<n<=32   : ranks cover [0,n); lanes >= n zero rows [n,32)
//   n>32      : 32 entries have rank < 32 -> all rows rank-written
__global__ void k_emit(const float4* __restrict__ pts,
                       float4* __restrict__ o_vox,
                       float* __restrict__ o_np) {
    int s = blockIdx.x * 8 + (threadIdx.x >> 5);
    if (s >= MAXV) return;
    int lane = threadIdx.x & 31;
    int v = g_vlist[s];
    int lin = v & 0x3FFFF;
    int n = (v >= 0) ? (v >> 18) : 0;    // clamped to CAP at pack time
    if (lane == 0) o_np[s] = (float)min(n, MAXP);
    float4* row = o_vox + (size_t)s * MAXP;
    const float4 z4 = make_float4(0.f, 0.f, 0.f, 0.f);

    if (n <= 32) {                       // common case (incl. empty slots)
        int m = n;                       // warp-uniform
        const int* buf = &g_vbuf[lin * CAP];
        int e0 = (v >= 0 && lane < m) ? buf[lane] : SENTINEL;
        int r0 = 0;
        for (int j = 0; j < m; j++) {    // m uniform across the warp
            int a = __shfl_sync(0xffffffffu, e0, j);
            r0 += (a < e0) ? 1 : 0;
        }
        if (lane < m) row[r0] = pts[e0];
        else          row[lane] = z4;    // zero padding rows [m, 32)
    } else {                             // rare: up to 64 entries, keep ranks < 32
        int m = n;                       // already min(cnt, CAP)
        const int* buf = &g_vbuf[lin * CAP];
        int e0 = (lane      < m) ? buf[lane]      : SENTINEL;
        int e1 = (lane + 32 < m) ? buf[lane + 32] : SENTINEL;
        int r0 = 0, r1 = 0;
        #pragma unroll
        for (int j = 0; j < 32; j++) {
            int a = __shfl_sync(0xffffffffu, e0, j);
            int b = __shfl_sync(0xffffffffu, e1, j);
            r0 += (a < e0) + (b < e0);
            r1 += (a < e1) + (b < e1);
        }
        if (e0 != SENTINEL && r0 < MAXP) row[r0] = pts[e0];
        if (e1 != SENTINEL && r1 < MAXP) row[r1] = pts[e1];
    }
}

// ---------------- launch ----------------
extern "C" void kernel_launch(void* const* d_in, const int* in_sizes, int n_in,
                              void* d_out, int out_size) {
    const float4* pts = (const float4*)d_in[0];
    int n = in_sizes[0] / 4;
    if (n > NPMAX) n = NPMAX;

    float* out    = (float*)d_out;
    float* o_coor = out + (size_t)MAXV * MAXP * 4;   // 5,120,000
    float* o_np   = o_coor + (size_t)MAXV * 3;       // +120,000

    int nb = (n + CHUNK - 1) / CHUNK;                // 1172 for n = 2.4M

    k_init <<<(NVOX + 255) / 256, 256>>>(o_coor);
    k_point<<<(n + 255) / 256, 256>>>(pts, n);
    k_hist <<<(NVOX + 1023) / 1024, 1024>>>();
    k_off  <<<1, 1024>>>();
    k_rank <<<nb, 256>>>(pts, n, o_coor);
    k_emit <<<(MAXV + 7) / 8, 256>>>(pts, (float4*)out, o_np);
}